// round 16
// baseline (speedup 1.0000x reference)
#include <cuda_runtime.h>
#include <math.h>

#define BB   64
#define TIN  128
#define NIN  256
#define MM   1024
#define OO   512
#define LMM  2048
#define TDEC 64
#define G3   3072
typedef unsigned long long ull;

// ---------------- scratch ----------------
__device__ float g_xt[TIN * BB * NIN];
__device__ float g_gi[TIN * BB * G3];
__device__ float g_seq0[TIN * BB * MM];
__device__ float g_e0A[BB * MM], g_e0B[BB * MM];
__device__ float g_e1A[BB * MM], g_e1B[BB * MM];
__device__ float g_hT0A[BB * MM], g_hT0B[BB * MM];
__device__ float g_hT1A[BB * MM], g_hT1B[BB * MM];
__device__ float g_yA[BB * OO], g_yB[BB * OO];
__device__ float g_zpre[BB * LMM];
__device__ float g_z[BB * LMM];
__device__ float g_l2p[2 * BB * OO];
__device__ unsigned g_barc, g_barg;
// tf32 pre-converted weights
__device__ float g_tWih0[G3 * OO];
__device__ float g_tWhh0[G3 * MM];
__device__ float g_tWih1[G3 * MM];
__device__ float g_tWhh1[G3 * MM];
__device__ float g_tfc1[LMM * MM];
__device__ float g_tfc2[OO * LMM];

// ---------------- helpers ----------------
__device__ __forceinline__ float sigf(float x) { return 1.f / (1.f + expf(-x)); }
__device__ __forceinline__ unsigned cvtTF(float x) {
    unsigned u; asm("cvt.rna.tf32.f32 %0, %1;" : "=r"(u) : "f"(x)); return u;
}
__device__ __forceinline__ void mma8(float* c, unsigned a0, unsigned a1, unsigned a2, unsigned a3,
                                     unsigned b0, unsigned b1) {
    asm("mma.sync.aligned.m16n8k8.row.col.f32.tf32.tf32.f32 "
        "{%0,%1,%2,%3},{%4,%5,%6,%7},{%8,%9},{%0,%1,%2,%3};"
        : "+f"(c[0]), "+f"(c[1]), "+f"(c[2]), "+f"(c[3])
        : "r"(a0), "r"(a1), "r"(a2), "r"(a3), "r"(b0), "r"(b1));
}

__device__ __forceinline__ void gbar() {
    __syncthreads();
    __threadfence();
    if (threadIdx.x == 0) {
        unsigned gen = ((volatile unsigned*)&g_barg)[0];
        if (atomicAdd(&g_barc, 1u) == gridDim.x - 1) {
            g_barc = 0;
            __threadfence();
            atomicAdd(&g_barg, 1u);
        } else {
            while (((volatile unsigned*)&g_barg)[0] == gen) {}
        }
    }
    __syncthreads();
}

// ================= encoder: persistent tf32-MMA layer, 128-k chunks =========
#define WS_LD 1028
#define HT_LD 132
#define ENC2_SM ((24 * WS_LD + 2 * 64 * HT_LD) * 4)   // 166272 B

__global__ void __launch_bounds__(256) enc_mma(
    const float* __restrict__ Whh, const float* __restrict__ bhh,
    const float* __restrict__ giB,
    float* hA, float* hB, float* hTA, float* hTB,
    float* seq)
{
    extern __shared__ float sm[];
    float* ws  = sm;                      // 24 x 1028
    float* ht0 = sm + 24 * WS_LD;         // 64 x 132
    float* ht1 = ht0 + 64 * HT_LD;
    int tid = threadIdx.x;
    int lane = tid & 31, warp = tid >> 5;
    int g = lane >> 2, t4 = lane & 3;
    int mi = warp & 3, kh = warp >> 2;
    int cBase = blockIdx.x * 8;

    for (int i = tid; i < 24 * 256; i += 256) {
        int r = i >> 8, kq = i & 255;
        int gRow = (r >> 3) * MM + cBase + (r & 7);
        float4 v = __ldg((const float4*)(Whh + (size_t)gRow * MM + kq * 4));
        uint4 u;
        u.x = cvtTF(v.x); u.y = cvtTF(v.y); u.z = cvtTF(v.z); u.w = cvtTF(v.w);
        *(uint4*)&ws[r * WS_LD + kq * 4] = u;
    }
    int c0 = cBase + 2 * t4;
    float br0 = bhh[c0],          br1 = bhh[c0 + 1];
    float bz0 = bhh[MM + c0],     bz1 = bhh[MM + c0 + 1];
    float bn0 = bhh[2 * MM + c0], bn1 = bhh[2 * MM + c0 + 1];
    __syncthreads();

    for (int t = 0; t < TIN; t++) {
        const float* hin  = (t & 1) ? hB : hA;
        float* hout       = (t & 1) ? hA : hB;
        const float* hinT = (t & 1) ? hTB : hTA;
        float* houtT      = (t & 1) ? hTA : hTB;

        float acc[3][4];
#pragma unroll
        for (int n = 0; n < 3; n++)
#pragma unroll
            for (int i = 0; i < 4; i++) acc[n][i] = 0.f;

        // stage chunk 0 (64 rows x 128 k)
#pragma unroll
        for (int i = 0; i < 8; i++) {
            int q = tid + i * 256;
            int row = q >> 5, kq = q & 31;
            float4 v = __ldcg((const float4*)(hinT + (size_t)row * MM + kq * 4));
            *(float4*)&ht0[row * HT_LD + kq * 4] = v;
        }
        __syncthreads();

#pragma unroll 1
        for (int ch = 0; ch < 8; ch++) {
            float* cur = (ch & 1) ? ht1 : ht0;
            float* nxt = (ch & 1) ? ht0 : ht1;
            float4 pf[8];
            if (ch < 7) {
#pragma unroll
                for (int i = 0; i < 8; i++) {
                    int q = tid + i * 256;
                    int row = q >> 5, kq = q & 31;
                    pf[i] = __ldcg((const float4*)(hinT + (size_t)row * MM + (ch + 1) * 128 + kq * 4));
                }
            }
            const unsigned* curu = (const unsigned*)cur;
            const unsigned* wsu  = (const unsigned*)ws;
            int arow0 = (16 * mi + g) * HT_LD;
            int arow1 = arow0 + 8 * HT_LD;
#pragma unroll
            for (int j = 0; j < 8; j++) {
                int k0 = (2 * j + kh) * 8;
                unsigned a0 = curu[arow0 + k0 + t4];
                unsigned a1 = curu[arow1 + k0 + t4];
                unsigned a2 = curu[arow0 + k0 + t4 + 4];
                unsigned a3 = curu[arow1 + k0 + t4 + 4];
                int kg = ch * 128 + k0 + t4;
#pragma unroll
                for (int nt = 0; nt < 3; nt++) {
                    unsigned b0 = wsu[(nt * 8 + g) * WS_LD + kg];
                    unsigned b1 = wsu[(nt * 8 + g) * WS_LD + kg + 4];
                    mma8(acc[nt], a0, a1, a2, a3, b0, b1);
                }
            }
            if (ch < 7) {
#pragma unroll
                for (int i = 0; i < 8; i++) {
                    int q = tid + i * 256;
                    int row = q >> 5, kq = q & 31;
                    *(float4*)&nxt[row * HT_LD + kq * 4] = pf[i];
                }
            }
            __syncthreads();
        }

        float* red = ht1;
        if (kh == 1) {
#pragma unroll
            for (int n = 0; n < 3; n++)
#pragma unroll
                for (int i = 0; i < 4; i++)
                    red[(mi * 32 + lane) * 12 + n * 4 + i] = acc[n][i];
        }
        __syncthreads();
        if (kh == 0) {
#pragma unroll
            for (int n = 0; n < 3; n++)
#pragma unroll
                for (int i = 0; i < 4; i++)
                    acc[n][i] += red[(mi * 32 + lane) * 12 + n * 4 + i];

            int rbase = 16 * mi + g;
#pragma unroll
            for (int half = 0; half < 2; half++) {
                int row = rbase + half * 8;
                float gr0 = acc[0][2 * half], gr1 = acc[0][2 * half + 1];
                float gz0 = acc[1][2 * half], gz1 = acc[1][2 * half + 1];
                float gn0 = acc[2][2 * half], gn1 = acc[2][2 * half + 1];
                const float* gi = giB + ((size_t)t * BB + row) * G3;
                float2 gir = *(const float2*)(gi + c0);
                float2 giz = *(const float2*)(gi + MM + c0);
                float2 gin = *(const float2*)(gi + 2 * MM + c0);
                float2 hp = __ldcg((const float2*)(hin + (size_t)row * MM + c0));
                float R0 = sigf(gir.x + gr0 + br0);
                float R1 = sigf(gir.y + gr1 + br1);
                float Z0 = sigf(giz.x + gz0 + bz0);
                float Z1 = sigf(giz.y + gz1 + bz1);
                float N0 = tanhf(gin.x + R0 * (gn0 + bn0));
                float N1 = tanhf(gin.y + R1 * (gn1 + bn1));
                float2 ho = {(1.f - Z0) * N0 + Z0 * hp.x, (1.f - Z1) * N1 + Z1 * hp.y};
                *(float2*)(hout + (size_t)row * MM + c0) = ho;
                float2 hoT = {__uint_as_float(cvtTF(ho.x)), __uint_as_float(cvtTF(ho.y))};
                *(float2*)(houtT + (size_t)row * MM + c0) = hoT;
                if (seq) *(float2*)(seq + ((size_t)t * BB + row) * MM + c0) = ho;
            }
        }
        gbar();
    }
}

// ================= decoder GRU phase: tf32 MMA, 128-k chunks ================
#define ALD 132
__device__ __forceinline__ void phase_gru_mma(
    const float* x, int Kx, const float* WihT,
    const float* hin, float* hout, const float* WhhT,
    const float* bih, const float* bhh,
    float* sm, int tid)
{
    float* wc0 = sm;                  // 24*132 = 3168
    float* wc1 = sm + 3168;
    float* ac0 = sm + 6336;           // 64*132 = 8448
    float* ac1 = ac0 + 8448;
    int lane = tid & 31, warp = tid >> 5;
    int g = lane >> 2, t4 = lane & 3;
    int mi = warp & 3, kh = warp >> 2;
    int cBase = blockIdx.x * 8;
    int xc = Kx / 128;
    int NC = xc + 8;

    float accI[3][4], accH[3][4];
#pragma unroll
    for (int n = 0; n < 3; n++)
#pragma unroll
        for (int i = 0; i < 4; i++) { accI[n][i] = 0.f; accH[n][i] = 0.f; }

#pragma unroll
    for (int i = 0; i < 8; i++) {
        int q = tid + i * 256, row = q >> 5, kq = q & 31;
        float4 v = __ldcg((const float4*)(x + (size_t)row * Kx + kq * 4));
        uint4 u = {cvtTF(v.x), cvtTF(v.y), cvtTF(v.z), cvtTF(v.w)};
        *(uint4*)&ac0[row * ALD + kq * 4] = u;
    }
#pragma unroll
    for (int i = 0; i < 3; i++) {
        int q = tid + i * 256;
        int row = q >> 5, kq = q & 31;
        int gRow = (row >> 3) * MM + cBase + (row & 7);
        float4 v = __ldg((const float4*)(WihT + (size_t)gRow * Kx + kq * 4));
        *(float4*)&wc0[row * ALD + kq * 4] = v;
    }
    __syncthreads();

#pragma unroll 1
    for (int ch = 0; ch < NC; ch++) {
        float* ac  = (ch & 1) ? ac1 : ac0;
        float* wc  = (ch & 1) ? wc1 : wc0;
        float* acn = (ch & 1) ? ac0 : ac1;
        float* wcn = (ch & 1) ? wc0 : wc1;
        float4 pa[8]; float4 pw[3];
        if (ch + 1 < NC) {
            int nc = ch + 1;
            const float* asrc; const float* wsrc; int K2, off;
            if (nc < xc) { asrc = x;   wsrc = WihT; K2 = Kx; off = nc * 128; }
            else         { asrc = hin; wsrc = WhhT; K2 = MM; off = (nc - xc) * 128; }
#pragma unroll
            for (int i = 0; i < 8; i++) {
                int q = tid + i * 256, row = q >> 5, kq = q & 31;
                pa[i] = __ldcg((const float4*)(asrc + (size_t)row * K2 + off + kq * 4));
            }
#pragma unroll
            for (int i = 0; i < 3; i++) {
                int q = tid + i * 256;
                int row = q >> 5, kq = q & 31;
                int gRow = (row >> 3) * MM + cBase + (row & 7);
                pw[i] = __ldg((const float4*)(wsrc + (size_t)gRow * K2 + off + kq * 4));
            }
        }
        const unsigned* au = (const unsigned*)ac;
        const unsigned* wu = (const unsigned*)wc;
        int arow0 = (16 * mi + g) * ALD;
        int arow1 = arow0 + 8 * ALD;
        float (*acc)[4] = (ch < xc) ? accI : accH;
#pragma unroll
        for (int j = 0; j < 8; j++) {
            int k0 = (2 * j + kh) * 8;
            unsigned a0 = au[arow0 + k0 + t4];
            unsigned a1 = au[arow1 + k0 + t4];
            unsigned a2 = au[arow0 + k0 + t4 + 4];
            unsigned a3 = au[arow1 + k0 + t4 + 4];
#pragma unroll
            for (int nt = 0; nt < 3; nt++) {
                unsigned b0 = wu[(nt * 8 + g) * ALD + k0 + t4];
                unsigned b1 = wu[(nt * 8 + g) * ALD + k0 + t4 + 4];
                mma8(acc[nt], a0, a1, a2, a3, b0, b1);
            }
        }
        if (ch + 1 < NC) {
#pragma unroll
            for (int i = 0; i < 8; i++) {
                int q = tid + i * 256, row = q >> 5, kq = q & 31;
                uint4 u = {cvtTF(pa[i].x), cvtTF(pa[i].y), cvtTF(pa[i].z), cvtTF(pa[i].w)};
                *(uint4*)&acn[row * ALD + kq * 4] = u;
            }
#pragma unroll
            for (int i = 0; i < 3; i++) {
                int q = tid + i * 256;
                int row = q >> 5, kq = q & 31;
                *(float4*)&wcn[row * ALD + kq * 4] = pw[i];
            }
        }
        __syncthreads();
    }

    float* red = ac0;
    if (kh == 1) {
#pragma unroll
        for (int n = 0; n < 3; n++)
#pragma unroll
            for (int i = 0; i < 4; i++) {
                red[(mi * 32 + lane) * 24 + n * 4 + i]      = accI[n][i];
                red[(mi * 32 + lane) * 24 + 12 + n * 4 + i] = accH[n][i];
            }
    }
    __syncthreads();
    if (kh == 0) {
#pragma unroll
        for (int n = 0; n < 3; n++)
#pragma unroll
            for (int i = 0; i < 4; i++) {
                accI[n][i] += red[(mi * 32 + lane) * 24 + n * 4 + i];
                accH[n][i] += red[(mi * 32 + lane) * 24 + 12 + n * 4 + i];
            }
        int c0 = cBase + 2 * t4;
        float2 bri = *(const float2*)(bih + c0);
        float2 bzi = *(const float2*)(bih + MM + c0);
        float2 bni = *(const float2*)(bih + 2 * MM + c0);
        float2 brh = *(const float2*)(bhh + c0);
        float2 bzh = *(const float2*)(bhh + MM + c0);
        float2 bnh = *(const float2*)(bhh + 2 * MM + c0);
#pragma unroll
        for (int half = 0; half < 2; half++) {
            int row = 16 * mi + g + half * 8;
            float2 hp = __ldcg((const float2*)(hin + (size_t)row * MM + c0));
            float R0 = sigf(accI[0][2*half]   + bri.x + accH[0][2*half]   + brh.x);
            float R1 = sigf(accI[0][2*half+1] + bri.y + accH[0][2*half+1] + brh.y);
            float Z0 = sigf(accI[1][2*half]   + bzi.x + accH[1][2*half]   + bzh.x);
            float Z1 = sigf(accI[1][2*half+1] + bzi.y + accH[1][2*half+1] + bzh.y);
            float N0 = tanhf(accI[2][2*half]   + bni.x + R0 * (accH[2][2*half]   + bnh.x));
            float N1 = tanhf(accI[2][2*half+1] + bni.y + R1 * (accH[2][2*half+1] + bnh.y));
            float2 ho = {(1.f - Z0) * N0 + Z0 * hp.x, (1.f - Z1) * N1 + Z1 * hp.y};
            *(float2*)(hout + (size_t)row * MM + c0) = ho;
        }
    }
}

// ================= fc1: tf32 MMA, 128-k chunks ==============================
__device__ __forceinline__ void phase_fc1_mma(
    const float* A, const float* WT, const float* bias, float* sm, int tid)
{
    float* wc0 = sm;                 // 16*132 = 2112
    float* wc1 = sm + 2112;
    float* ac0 = sm + 4224;          // 64*132 = 8448
    float* ac1 = ac0 + 8448;
    int lane = tid & 31, warp = tid >> 5;
    int g = lane >> 2, t4 = lane & 3;
    int mi = warp & 3, kh = warp >> 2;
    int cBase = blockIdx.x * 16;

    float acc[2][4];
#pragma unroll
    for (int n = 0; n < 2; n++)
#pragma unroll
        for (int i = 0; i < 4; i++) acc[n][i] = 0.f;

#pragma unroll
    for (int i = 0; i < 8; i++) {
        int q = tid + i * 256, row = q >> 5, kq = q & 31;
        float4 v = __ldcg((const float4*)(A + (size_t)row * MM + kq * 4));
        uint4 u = {cvtTF(v.x), cvtTF(v.y), cvtTF(v.z), cvtTF(v.w)};
        *(uint4*)&ac0[row * ALD + kq * 4] = u;
    }
#pragma unroll
    for (int i = 0; i < 2; i++) {
        int q = tid + i * 256;
        int row = q >> 5, kq = q & 31;
        float4 v = __ldg((const float4*)(WT + (size_t)(cBase + row) * MM + kq * 4));
        *(float4*)&wc0[row * ALD + kq * 4] = v;
    }
    __syncthreads();

#pragma unroll 1
    for (int ch = 0; ch < 8; ch++) {
        float* ac  = (ch & 1) ? ac1 : ac0;
        float* wc  = (ch & 1) ? wc1 : wc0;
        float* acn = (ch & 1) ? ac0 : ac1;
        float* wcn = (ch & 1) ? wc0 : wc1;
        float4 pa[8]; float4 pw[2];
        if (ch < 7) {
            int off = (ch + 1) * 128;
#pragma unroll
            for (int i = 0; i < 8; i++) {
                int q = tid + i * 256, row = q >> 5, kq = q & 31;
                pa[i] = __ldcg((const float4*)(A + (size_t)row * MM + off + kq * 4));
            }
#pragma unroll
            for (int i = 0; i < 2; i++) {
                int q = tid + i * 256;
                int row = q >> 5, kq = q & 31;
                pw[i] = __ldg((const float4*)(WT + (size_t)(cBase + row) * MM + off + kq * 4));
            }
        }
        const unsigned* au = (const unsigned*)ac;
        const unsigned* wu = (const unsigned*)wc;
        int arow0 = (16 * mi + g) * ALD;
        int arow1 = arow0 + 8 * ALD;
#pragma unroll
        for (int j = 0; j < 8; j++) {
            int k0 = (2 * j + kh) * 8;
            unsigned a0 = au[arow0 + k0 + t4];
            unsigned a1 = au[arow1 + k0 + t4];
            unsigned a2 = au[arow0 + k0 + t4 + 4];
            unsigned a3 = au[arow1 + k0 + t4 + 4];
#pragma unroll
            for (int nt = 0; nt < 2; nt++) {
                unsigned b0 = wu[(nt * 8 + g) * ALD + k0 + t4];
                unsigned b1 = wu[(nt * 8 + g) * ALD + k0 + t4 + 4];
                mma8(acc[nt], a0, a1, a2, a3, b0, b1);
            }
        }
        if (ch < 7) {
#pragma unroll
            for (int i = 0; i < 8; i++) {
                int q = tid + i * 256, row = q >> 5, kq = q & 31;
                uint4 u = {cvtTF(pa[i].x), cvtTF(pa[i].y), cvtTF(pa[i].z), cvtTF(pa[i].w)};
                *(uint4*)&acn[row * ALD + kq * 4] = u;
            }
#pragma unroll
            for (int i = 0; i < 2; i++) {
                int q = tid + i * 256;
                int row = q >> 5, kq = q & 31;
                *(float4*)&wcn[row * ALD + kq * 4] = pw[i];
            }
        }
        __syncthreads();
    }

    float* red = ac0;
    if (kh == 1) {
#pragma unroll
        for (int n = 0; n < 2; n++)
#pragma unroll
            for (int i = 0; i < 4; i++)
                red[(mi * 32 + lane) * 8 + n * 4 + i] = acc[n][i];
    }
    __syncthreads();
    if (kh == 0) {
#pragma unroll
        for (int n = 0; n < 2; n++)
#pragma unroll
            for (int i = 0; i < 4; i++)
                acc[n][i] += red[(mi * 32 + lane) * 8 + n * 4 + i];
#pragma unroll
        for (int half = 0; half < 2; half++) {
            int row = 16 * mi + g + half * 8;
#pragma unroll
            for (int nt = 0; nt < 2; nt++) {
                int c = cBase + nt * 8 + 2 * t4;
                float2 bv = *(const float2*)(bias + c);
                float2 o = {acc[nt][2 * half] + bv.x, acc[nt][2 * half + 1] + bv.y};
                *(float2*)(g_zpre + (size_t)row * LMM + c) = o;
            }
        }
    }
}

// ================= fc2: tf32 MMA, K-split + act hi/lo, 128-k chunks =========
__device__ __forceinline__ void phase_fc2_mma(const float* WT, float* sm, int tid)
{
    float* wc0 = sm;                 // 8*132 = 1056
    float* wc1 = sm + 1056;
    float* hi0 = sm + 2112;          // 8448 each
    float* lo0 = hi0 + 8448;
    float* hi1 = lo0 + 8448;
    float* lo1 = hi1 + 8448;
    int lane = tid & 31, warp = tid >> 5;
    int g = lane >> 2, t4 = lane & 3;
    int mi = warp & 3, kh = warp >> 2;
    int cBase = (blockIdx.x >> 1) * 8;
    int ksp = blockIdx.x & 1;
    int kOff = ksp * 1024;

    float acc[4] = {0.f, 0.f, 0.f, 0.f};

#pragma unroll
    for (int i = 0; i < 8; i++) {
        int q = tid + i * 256, row = q >> 5, kq = q & 31;
        float4 v = __ldcg((const float4*)(g_z + (size_t)row * LMM + kOff + kq * 4));
        uint4 uh = {cvtTF(v.x), cvtTF(v.y), cvtTF(v.z), cvtTF(v.w)};
        uint4 ul = {cvtTF(v.x - __uint_as_float(uh.x)), cvtTF(v.y - __uint_as_float(uh.y)),
                    cvtTF(v.z - __uint_as_float(uh.z)), cvtTF(v.w - __uint_as_float(uh.w))};
        *(uint4*)&hi0[row * ALD + kq * 4] = uh;
        *(uint4*)&lo0[row * ALD + kq * 4] = ul;
    }
    {
        int row = tid >> 5, kq = tid & 31;
        float4 v = __ldg((const float4*)(WT + (size_t)(cBase + row) * LMM + kOff + kq * 4));
        *(float4*)&wc0[row * ALD + kq * 4] = v;
    }
    __syncthreads();

#pragma unroll 1
    for (int ch = 0; ch < 8; ch++) {
        float* hi  = (ch & 1) ? hi1 : hi0;
        float* lo  = (ch & 1) ? lo1 : lo0;
        float* wc  = (ch & 1) ? wc1 : wc0;
        float* hin_ = (ch & 1) ? hi0 : hi1;
        float* lon = (ch & 1) ? lo0 : lo1;
        float* wcn = (ch & 1) ? wc0 : wc1;
        float4 pa[8]; float4 pw;
        if (ch < 7) {
            int off = kOff + (ch + 1) * 128;
#pragma unroll
            for (int i = 0; i < 8; i++) {
                int q = tid + i * 256, row = q >> 5, kq = q & 31;
                pa[i] = __ldcg((const float4*)(g_z + (size_t)row * LMM + off + kq * 4));
            }
            {
                int row = tid >> 5, kq = tid & 31;
                pw = __ldg((const float4*)(WT + (size_t)(cBase + row) * LMM + off + kq * 4));
            }
        }
        const unsigned* hu = (const unsigned*)hi;
        const unsigned* lu = (const unsigned*)lo;
        const unsigned* wu = (const unsigned*)wc;
        int arow0 = (16 * mi + g) * ALD;
        int arow1 = arow0 + 8 * ALD;
#pragma unroll
        for (int j = 0; j < 8; j++) {
            int k0 = (2 * j + kh) * 8;
            unsigned b0 = wu[g * ALD + k0 + t4];
            unsigned b1 = wu[g * ALD + k0 + t4 + 4];
            mma8(acc, hu[arow0 + k0 + t4], hu[arow1 + k0 + t4],
                      hu[arow0 + k0 + t4 + 4], hu[arow1 + k0 + t4 + 4], b0, b1);
            mma8(acc, lu[arow0 + k0 + t4], lu[arow1 + k0 + t4],
                      lu[arow0 + k0 + t4 + 4], lu[arow1 + k0 + t4 + 4], b0, b1);
        }
        if (ch < 7) {
#pragma unroll
            for (int i = 0; i < 8; i++) {
                int q = tid + i * 256, row = q >> 5, kq = q & 31;
                uint4 uh = {cvtTF(pa[i].x), cvtTF(pa[i].y), cvtTF(pa[i].z), cvtTF(pa[i].w)};
                uint4 ul = {cvtTF(pa[i].x - __uint_as_float(uh.x)), cvtTF(pa[i].y - __uint_as_float(uh.y)),
                            cvtTF(pa[i].z - __uint_as_float(uh.z)), cvtTF(pa[i].w - __uint_as_float(uh.w))};
                *(uint4*)&hin_[row * ALD + kq * 4] = uh;
                *(uint4*)&lon[row * ALD + kq * 4] = ul;
            }
            {
                int row = tid >> 5, kq = tid & 31;
                *(float4*)&wcn[row * ALD + kq * 4] = pw;
            }
        }
        __syncthreads();
    }

    float* red = hi0;
    if (kh == 1) {
#pragma unroll
        for (int i = 0; i < 4; i++)
            red[(mi * 32 + lane) * 4 + i] = acc[i];
    }
    __syncthreads();
    if (kh == 0) {
#pragma unroll
        for (int i = 0; i < 4; i++) acc[i] += red[(mi * 32 + lane) * 4 + i];
        int c0 = cBase + 2 * t4;
#pragma unroll
        for (int half = 0; half < 2; half++) {
            int row = 16 * mi + g + half * 8;
            float2 o = {acc[2 * half], acc[2 * half + 1]};
            *(float2*)(g_l2p + (size_t)ksp * BB * OO + (size_t)row * OO + c0) = o;
        }
    }
}

// ---------------- ln / softmax ----------------
__device__ __forceinline__ void phase_ln(const float* g, const float* bta, int tid)
{
    int b = blockIdx.x;
    float v[8];
    float s = 0.f, s2 = 0.f;
#pragma unroll
    for (int j = 0; j < 8; j++) {
        float t = __ldcg(&g_zpre[(size_t)b * LMM + tid + j * 256]);
        v[j] = t; s += t; s2 += t * t;
    }
    __shared__ float red[64];
#pragma unroll
    for (int o = 16; o; o >>= 1) {
        s += __shfl_down_sync(0xffffffffu, s, o);
        s2 += __shfl_down_sync(0xffffffffu, s2, o);
    }
    int w = tid >> 5, l = tid & 31;
    if (l == 0) { red[w] = s; red[32 + w] = s2; }
    __syncthreads();
    if (tid == 0) {
        float a = 0.f, a2 = 0.f;
        for (int i = 0; i < 8; i++) { a += red[i]; a2 += red[32 + i]; }
        red[0] = a; red[32] = a2;
    }
    __syncthreads();
    float mu = red[0] * (1.f / (float)LMM);
    float var = red[32] * (1.f / (float)LMM) - mu * mu;
    float rs = rsqrtf(var + 1e-5f);
#pragma unroll
    for (int j = 0; j < 8; j++) {
        int cc = tid + j * 256;
        float t = (v[j] - mu) * rs * g[cc] + bta[cc];
        g_z[(size_t)b * LMM + cc] = t * normcdff(t);
    }
}

__device__ __forceinline__ void phase_softmax2(
    float* out, int s, float* yout, const float* fc2b, int tid)
{
    int b = blockIdx.x;
    float v0 = __ldcg(&g_l2p[(size_t)b * OO + tid])
             + __ldcg(&g_l2p[(size_t)BB * OO + b * OO + tid]) + fc2b[tid];
    float v1 = __ldcg(&g_l2p[(size_t)b * OO + 256 + tid])
             + __ldcg(&g_l2p[(size_t)BB * OO + b * OO + 256 + tid]) + fc2b[256 + tid];
    out[((size_t)b * TDEC + s) * OO + tid] = v0;
    out[((size_t)b * TDEC + s) * OO + 256 + tid] = v1;

    __shared__ float sred[9];
    int w = tid >> 5, l = tid & 31;
    float m = fmaxf(v0, v1);
#pragma unroll
    for (int d = 16; d; d >>= 1) m = fmaxf(m, __shfl_down_sync(0xffffffffu, m, d));
    if (l == 0) sred[w] = m;
    __syncthreads();
    if (tid == 0) {
        float a = sred[0];
        for (int i = 1; i < 8; i++) a = fmaxf(a, sred[i]);
        sred[8] = a;
    }
    __syncthreads();
    float mx = sred[8];
    float e0 = expf(v0 - mx), e1 = expf(v1 - mx);
    float su = e0 + e1;
#pragma unroll
    for (int d = 16; d; d >>= 1) su += __shfl_down_sync(0xffffffffu, su, d);
    __syncthreads();
    if (l == 0) sred[w] = su;
    __syncthreads();
    if (tid == 0) {
        float a = 0.f;
        for (int i = 0; i < 8; i++) a += sred[i];
        sred[8] = a;
    }
    __syncthreads();
    float inv = 1.f / sred[8];
    yout[(size_t)b * OO + tid]       = e0 * inv;
    yout[(size_t)b * OO + 256 + tid] = e1 * inv;
}

__global__ void __launch_bounds__(256) dec_persist(
    float* __restrict__ out,
    float* yA, float* yB, float* h0A, float* h0B, float* h1A, float* h1B,
    const float* __restrict__ bih0, const float* __restrict__ bhh0,
    const float* __restrict__ bih1, const float* __restrict__ bhh1,
    const float* __restrict__ fc1b,
    const float* __restrict__ lng, const float* __restrict__ lnb,
    const float* __restrict__ fc2b)
{
    extern __shared__ float sm[];
    int tid = threadIdx.x;

    for (int s = 0; s < TDEC; s++) {
        const float* yin = (s & 1) ? yB : yA;
        float* yout      = (s & 1) ? yA : yB;
        const float* h0i = (s & 1) ? h0B : h0A;
        float* h0o       = (s & 1) ? h0A : h0B;
        const float* h1i = (s & 1) ? h1B : h1A;
        float* h1o       = (s & 1) ? h1A : h1B;

        phase_gru_mma(yin, OO, g_tWih0, h0i, h0o, g_tWhh0, bih0, bhh0, sm, tid);
        gbar();
        phase_gru_mma(h0o, MM, g_tWih1, h1i, h1o, g_tWhh1, bih1, bhh1, sm, tid);
        gbar();
        phase_fc1_mma(h1o, g_tfc1, fc1b, sm, tid);
        gbar();
        if (blockIdx.x < BB) phase_ln(lng, lnb, tid);
        gbar();
        phase_fc2_mma(g_tfc2, sm, tid);
        gbar();
        if (blockIdx.x < BB) phase_softmax2(out, s, yout, fc2b, tid);
        gbar();
    }
}

// ---------------- init / transpose / cvt / big GEMM ------------
__global__ void zero_init_kernel() {
    int i = blockIdx.x * blockDim.x + threadIdx.x;
    int stride = gridDim.x * blockDim.x;
    for (; i < BB * MM; i += stride) {
        g_e0A[i] = 0.f; g_e1A[i] = 0.f;
        g_hT0A[i] = 0.f; g_hT1A[i] = 0.f;
    }
}
__global__ void copy_y_kernel(const float* __restrict__ Y0) {
    int i = blockIdx.x * blockDim.x + threadIdx.x;
    if (i < BB * OO) g_yA[i] = Y0[i];
}
__global__ void transpose_x_kernel(const float* __restrict__ X) {
    int i = blockIdx.x * blockDim.x + threadIdx.x;
    int stride = gridDim.x * blockDim.x;
    const int total = TIN * BB * NIN;
    for (; i < total; i += stride) {
        int n = i % NIN;
        int r = i / NIN;
        int t = r / BB, b = r % BB;
        g_xt[i] = X[(b * TIN + t) * NIN + n];
    }
}
__global__ void cvt_w_kernel(const float* __restrict__ s, float* __restrict__ d, int n) {
    int i = blockIdx.x * blockDim.x + threadIdx.x;
    int st = gridDim.x * blockDim.x;
    for (; i < n; i += st) d[i] = __uint_as_float(cvtTF(s[i]));
}

__device__ __forceinline__ void fma2(ull& d, ull a, ull b) {
    asm("fma.rn.f32x2 %0, %1, %2, %0;" : "+l"(d) : "l"(a), "l"(b));
}

__global__ void __launch_bounds__(256) gemm_big_kernel(
    const float* __restrict__ A, const float* __restrict__ W,
    const float* __restrict__ bias, float* __restrict__ C,
    int K, int Cn)
{
    __shared__ __align__(16) float As[16][132];
    __shared__ __align__(16) float Bs[16][132];
    int tid = threadIdx.x;
    int tx = tid & 15, ty = tid >> 4;
    int r0 = blockIdx.y * 128, c0 = blockIdx.x * 128;
    ull acc[8][4];
#pragma unroll
    for (int i = 0; i < 8; i++)
#pragma unroll
        for (int j = 0; j < 4; j++) acc[i][j] = 0ull;
    for (int k0 = 0; k0 < K; k0 += 16) {
#pragma unroll
        for (int i = 0; i < 2; i++) {
            int q = tid + i * 256;
            int rr = q >> 2, kq = q & 3;
            float4 v = *(const float4*)(A + (size_t)(r0 + rr) * K + k0 + kq * 4);
            As[kq * 4 + 0][rr] = v.x; As[kq * 4 + 1][rr] = v.y;
            As[kq * 4 + 2][rr] = v.z; As[kq * 4 + 3][rr] = v.w;
        }
#pragma unroll
        for (int i = 0; i < 2; i++) {
            int q = tid + i * 256;
            int wn = q >> 2, kq = q & 3;
            float4 v = *(const float4*)(W + (size_t)(c0 + wn) * K + k0 + kq * 4);
            Bs[kq * 4 + 0][wn] = v.x; Bs[kq * 4 + 1][wn] = v.y;
            Bs[kq * 4 + 2][wn] = v.z; Bs[kq * 4 + 3][wn] = v.w;
        }
        __syncthreads();
#pragma unroll
        for (int kk = 0; kk < 16; kk++) {
            ulonglong2 bq0 = *(ulonglong2*)&Bs[kk][tx * 8];
            ulonglong2 bq1 = *(ulonglong2*)&Bs[kk][tx * 8 + 4];
            ull bp[4] = {bq0.x, bq0.y, bq1.x, bq1.y};
            float4 a0 = *(float4*)&As[kk][ty * 8];
            float4 a1 = *(float4*)&As[kk][ty * 8 + 4];
            float av[8] = {a0.x, a0.y, a0.z, a0.w, a1.x, a1.y, a1.z, a1.w};
#pragma unroll
            for (int i = 0; i < 8; i++) {
                ull ap;
                asm("mov.b64 %0, {%1,%1};" : "=l"(ap) : "f"(av[i]));
#pragma unroll
                for (int j = 0; j < 4; j++) fma2(acc[i][j], ap, bp[j]);
            }
        }
        __syncthreads();
    }
    int c = c0 + tx * 8;
    float4 bv0 = *(const float4*)(bias + c);
    float4 bv1 = *(const float4*)(bias + c + 4);
#pragma unroll
    for (int i = 0; i < 8; i++) {
        int r = r0 + ty * 8 + i;
        float2 p0, p1, p2, p3;
        asm("mov.b64 {%0,%1}, %2;" : "=f"(p0.x), "=f"(p0.y) : "l"(acc[i][0]));
        asm("mov.b64 {%0,%1}, %2;" : "=f"(p1.x), "=f"(p1.y) : "l"(acc[i][1]));
        asm("mov.b64 {%0,%1}, %2;" : "=f"(p2.x), "=f"(p2.y) : "l"(acc[i][2]));
        asm("mov.b64 {%0,%1}, %2;" : "=f"(p3.x), "=f"(p3.y) : "l"(acc[i][3]));
        float4 o0 = {p0.x + bv0.x, p0.y + bv0.y, p1.x + bv0.z, p1.y + bv0.w};
        float4 o1 = {p2.x + bv1.x, p2.y + bv1.y, p3.x + bv1.z, p3.y + bv1.w};
        *(float4*)(C + (size_t)r * Cn + c) = o0;
        *(float4*)(C + (size_t)r * Cn + c + 4) = o1;
    }
}

// ---------------- host launch ----------------
#define DEC_SM ((2 * 1056 + 4 * 8448) * 4)      // 143616 B (fc2 is max)

extern "C" void kernel_launch(void* const* d_in, const int* in_sizes, int n_in,
                              void* d_out, int out_size)
{
    const float* X        = (const float*)d_in[0];
    const float* Y0       = (const float*)d_in[1];
    const float* enc_Wih0 = (const float*)d_in[2];
    const float* enc_Whh0 = (const float*)d_in[3];
    const float* enc_bih0 = (const float*)d_in[4];
    const float* enc_bhh0 = (const float*)d_in[5];
    const float* enc_Wih1 = (const float*)d_in[6];
    const float* enc_Whh1 = (const float*)d_in[7];
    const float* enc_bih1 = (const float*)d_in[8];
    const float* enc_bhh1 = (const float*)d_in[9];
    const float* dec_Wih0 = (const float*)d_in[10];
    const float* dec_Whh0 = (const float*)d_in[11];
    const float* dec_bih0 = (const float*)d_in[12];
    const float* dec_bhh0 = (const float*)d_in[13];
    const float* dec_Wih1 = (const float*)d_in[14];
    const float* dec_Whh1 = (const float*)d_in[15];
    const float* dec_bih1 = (const float*)d_in[16];
    const float* dec_bhh1 = (const float*)d_in[17];
    const float* fc1_w    = (const float*)d_in[18];
    const float* fc1_b    = (const float*)d_in[19];
    const float* ln_g     = (const float*)d_in[20];
    const float* ln_b     = (const float*)d_in[21];
    const float* fc2_w    = (const float*)d_in[22];
    const float* fc2_b    = (const float*)d_in[23];
    float* out = (float*)d_out;

    float *xt, *gi, *seq0, *e0A, *e0B, *e1A, *e1B, *yA, *yB;
    float *hT0A, *hT0B, *hT1A, *hT1B;
    float *tWih0, *tWhh0, *tWih1, *tWhh1, *tfc1, *tfc2;
    cudaGetSymbolAddress((void**)&xt,   g_xt);
    cudaGetSymbolAddress((void**)&gi,   g_gi);
    cudaGetSymbolAddress((void**)&seq0, g_seq0);
    cudaGetSymbolAddress((void**)&e0A,  g_e0A);
    cudaGetSymbolAddress((void**)&e0B,  g_e0B);
    cudaGetSymbolAddress((void**)&e1A,  g_e1A);
    cudaGetSymbolAddress((void**)&e1B,  g_e1B);
    cudaGetSymbolAddress((void**)&hT0A, g_hT0A);
    cudaGetSymbolAddress((void**)&hT0B, g_hT0B);
    cudaGetSymbolAddress((void**)&hT1A, g_hT1A);
    cudaGetSymbolAddress((void**)&hT1B, g_hT1B);
    cudaGetSymbolAddress((void**)&yA,   g_yA);
    cudaGetSymbolAddress((void**)&yB,   g_yB);
    cudaGetSymbolAddress((void**)&tWih0, g_tWih0);
    cudaGetSymbolAddress((void**)&tWhh0, g_tWhh0);
    cudaGetSymbolAddress((void**)&tWih1, g_tWih1);
    cudaGetSymbolAddress((void**)&tWhh1, g_tWhh1);
    cudaGetSymbolAddress((void**)&tfc1, g_tfc1);
    cudaGetSymbolAddress((void**)&tfc2, g_tfc2);

    cudaFuncSetAttribute(enc_mma,     cudaFuncAttributeMaxDynamicSharedMemorySize, ENC2_SM);
    cudaFuncSetAttribute(dec_persist, cudaFuncAttributeMaxDynamicSharedMemorySize, DEC_SM);

    zero_init_kernel<<<256, 256>>>();
    copy_y_kernel<<<(BB * OO + 255) / 256, 256>>>(Y0);
    transpose_x_kernel<<<2048, 256>>>(X);
    cvt_w_kernel<<<1024, 256>>>(dec_Wih0, tWih0, G3 * OO);
    cvt_w_kernel<<<1024, 256>>>(dec_Whh0, tWhh0, G3 * MM);
    cvt_w_kernel<<<1024, 256>>>(dec_Wih1, tWih1, G3 * MM);
    cvt_w_kernel<<<1024, 256>>>(dec_Whh1, tWhh1, G3 * MM);
    cvt_w_kernel<<<1024, 256>>>(fc1_w, tfc1, LMM * MM);
    cvt_w_kernel<<<1024, 256>>>(fc2_w, tfc2, OO * LMM);

    const int R = TIN * BB;

    // encoder layer 0
    gemm_big_kernel<<<dim3(G3 / 128, R / 128), 256>>>(xt, enc_Wih0, enc_bih0, gi, NIN, G3);
    {
        const float* w = enc_Whh0; const float* b = enc_bhh0; const float* gp = gi;
        float* hA = e0A; float* hB = e0B; float* hTA = hT0A; float* hTB = hT0B; float* sq = seq0;
        void* args[] = {&w, &b, &gp, &hA, &hB, &hTA, &hTB, &sq};
        cudaLaunchCooperativeKernel((void*)enc_mma, dim3(128), dim3(256), args, (size_t)ENC2_SM, (cudaStream_t)0);
    }

    // encoder layer 1
    gemm_big_kernel<<<dim3(G3 / 128, R / 128), 256>>>(seq0, enc_Wih1, enc_bih1, gi, MM, G3);
    {
        const float* w = enc_Whh1; const float* b = enc_bhh1; const float* gp = gi;
        float* hA = e1A; float* hB = e1B; float* hTA = hT1A; float* hTB = hT1B; float* sq = nullptr;
        void* args[] = {&w, &b, &gp, &hA, &hB, &hTA, &hTB, &sq};
        cudaLaunchCooperativeKernel((void*)enc_mma, dim3(128), dim3(256), args, (size_t)ENC2_SM, (cudaStream_t)0);
    }

    // decoder: one persistent kernel, all 64 steps
    {
        float* outp = out;
        void* args[] = {&outp, &yA, &yB, &e0A, &e0B, &e1A, &e1B,
                        (void*)&dec_bih0, (void*)&dec_bhh0,
                        (void*)&dec_bih1, (void*)&dec_bhh1,
                        (void*)&fc1_b, (void*)&ln_g, (void*)&ln_b, (void*)&fc2_b};
        cudaLaunchCooperativeKernel((void*)dec_persist, dim3(128), dim3(256), args, (size_t)DEC_SM, (cudaStream_t)0);
    }
}

// round 17
// speedup vs baseline: 1.4849x; 1.4849x over previous
#include <cuda_runtime.h>
#include <math.h>

#define BB   64
#define TIN  128
#define NIN  256
#define MM   1024
#define OO   512
#define LMM  2048
#define TDEC 64
#define G3   3072
typedef unsigned long long ull;

// ---------------- scratch ----------------
__device__ float g_xt[TIN * BB * NIN];
__device__ float g_gi[TIN * BB * G3];
__device__ float g_seq0[TIN * BB * MM];
__device__ float g_e0A[BB * MM], g_e0B[BB * MM];
__device__ float g_e1A[BB * MM], g_e1B[BB * MM];
__device__ float g_hT0A[BB * MM], g_hT0B[BB * MM];   // tf32 copies (enc + dec gru0)
__device__ float g_hT1A[BB * MM], g_hT1B[BB * MM];   // tf32 copies (enc + dec gru1)
__device__ float g_yTA[BB * OO], g_yTB[BB * OO];     // tf32 y feedback
__device__ float g_zpre[BB * LMM];
__device__ float g_zhi[BB * LMM], g_zlo[BB * LMM];   // gelu(z) hi/lo tf32 split
__device__ float g_l2p[2 * BB * OO];
__device__ unsigned g_barc, g_barg;
// tf32 pre-converted weights
__device__ float g_tWih0[G3 * OO];
__device__ float g_tWhh0[G3 * MM];
__device__ float g_tWih1[G3 * MM];
__device__ float g_tWhh1[G3 * MM];
__device__ float g_tfc1[LMM * MM];
__device__ float g_tfc2[OO * LMM];

// ---------------- helpers ----------------
__device__ __forceinline__ float sigf(float x) { return 1.f / (1.f + expf(-x)); }
__device__ __forceinline__ unsigned cvtTF(float x) {
    unsigned u; asm("cvt.rna.tf32.f32 %0, %1;" : "=r"(u) : "f"(x)); return u;
}
__device__ __forceinline__ void mma8(float* c, unsigned a0, unsigned a1, unsigned a2, unsigned a3,
                                     unsigned b0, unsigned b1) {
    asm("mma.sync.aligned.m16n8k8.row.col.f32.tf32.tf32.f32 "
        "{%0,%1,%2,%3},{%4,%5,%6,%7},{%8,%9},{%0,%1,%2,%3};"
        : "+f"(c[0]), "+f"(c[1]), "+f"(c[2]), "+f"(c[3])
        : "r"(a0), "r"(a1), "r"(a2), "r"(a3), "r"(b0), "r"(b1));
}
__device__ __forceinline__ void cpa16(unsigned saddr, const void* g) {
    asm volatile("cp.async.cg.shared.global [%0], [%1], 16;" :: "r"(saddr), "l"(g));
}
__device__ __forceinline__ void cpaCommit() { asm volatile("cp.async.commit_group;"); }
__device__ __forceinline__ void cpaWait0()  { asm volatile("cp.async.wait_group 0;" ::: "memory"); }
__device__ __forceinline__ unsigned s2u(const void* p) {
    return (unsigned)__cvta_generic_to_shared(p);
}

__device__ __forceinline__ void gbar() {
    __syncthreads();
    __threadfence();
    if (threadIdx.x == 0) {
        unsigned gen = ((volatile unsigned*)&g_barg)[0];
        if (atomicAdd(&g_barc, 1u) == gridDim.x - 1) {
            g_barc = 0;
            __threadfence();
            atomicAdd(&g_barg, 1u);
        } else {
            while (((volatile unsigned*)&g_barg)[0] == gen) {}
        }
    }
    __syncthreads();
}

// ================= encoder: persistent tf32-MMA layer, cp.async 128-k =======
#define WS_LD 1028
#define HT_LD 132
#define ENC2_SM ((24 * WS_LD + 2 * 64 * HT_LD) * 4)   // 166272 B

__global__ void __launch_bounds__(256) enc_mma(
    const float* __restrict__ Whh, const float* __restrict__ bhh,
    const float* __restrict__ giB,
    float* hA, float* hB, float* hTA, float* hTB,
    float* seq)
{
    extern __shared__ float sm[];
    float* ws  = sm;                      // 24 x 1028 (tf32 bits)
    float* ht0 = sm + 24 * WS_LD;         // 64 x 132
    float* ht1 = ht0 + 64 * HT_LD;
    int tid = threadIdx.x;
    int lane = tid & 31, warp = tid >> 5;
    int g = lane >> 2, t4 = lane & 3;
    int mi = warp & 3, kh = warp >> 2;
    int cBase = blockIdx.x * 8;
    unsigned uht0 = s2u(ht0), uht1 = s2u(ht1);

    for (int i = tid; i < 24 * 256; i += 256) {
        int r = i >> 8, kq = i & 255;
        int gRow = (r >> 3) * MM + cBase + (r & 7);
        float4 v = __ldg((const float4*)(Whh + (size_t)gRow * MM + kq * 4));
        uint4 u;
        u.x = cvtTF(v.x); u.y = cvtTF(v.y); u.z = cvtTF(v.z); u.w = cvtTF(v.w);
        *(uint4*)&ws[r * WS_LD + kq * 4] = u;
    }
    int c0 = cBase + 2 * t4;
    float br0 = bhh[c0],          br1 = bhh[c0 + 1];
    float bz0 = bhh[MM + c0],     bz1 = bhh[MM + c0 + 1];
    float bn0 = bhh[2 * MM + c0], bn1 = bhh[2 * MM + c0 + 1];
    __syncthreads();

    int srow = tid >> 5, skq = tid & 31;  // staging coords (8 iters: row += 8)

    for (int t = 0; t < TIN; t++) {
        const float* hin  = (t & 1) ? hB : hA;
        float* hout       = (t & 1) ? hA : hB;
        const float* hinT = (t & 1) ? hTB : hTA;
        float* houtT      = (t & 1) ? hTA : hTB;

        float acc[3][4];
#pragma unroll
        for (int n = 0; n < 3; n++)
#pragma unroll
            for (int i = 0; i < 4; i++) acc[n][i] = 0.f;

        // stage chunk 0 (64 rows x 128 k)
#pragma unroll
        for (int i = 0; i < 8; i++) {
            int row = srow + i * 8;
            cpa16(uht0 + (row * HT_LD + skq * 4) * 4, hinT + (size_t)row * MM + skq * 4);
        }
        cpaCommit();
        cpaWait0();
        __syncthreads();

#pragma unroll 1
        for (int ch = 0; ch < 8; ch++) {
            float* cur = (ch & 1) ? ht1 : ht0;
            unsigned unxt = (ch & 1) ? uht0 : uht1;
            if (ch < 7) {
#pragma unroll
                for (int i = 0; i < 8; i++) {
                    int row = srow + i * 8;
                    cpa16(unxt + (row * HT_LD + skq * 4) * 4,
                          hinT + (size_t)row * MM + (ch + 1) * 128 + skq * 4);
                }
                cpaCommit();
            }
            const unsigned* curu = (const unsigned*)cur;
            const unsigned* wsu  = (const unsigned*)ws;
            int arow0 = (16 * mi + g) * HT_LD;
            int arow1 = arow0 + 8 * HT_LD;
#pragma unroll
            for (int j = 0; j < 8; j++) {
                int k0 = (2 * j + kh) * 8;
                unsigned a0 = curu[arow0 + k0 + t4];
                unsigned a1 = curu[arow1 + k0 + t4];
                unsigned a2 = curu[arow0 + k0 + t4 + 4];
                unsigned a3 = curu[arow1 + k0 + t4 + 4];
                int kg = ch * 128 + k0 + t4;
#pragma unroll
                for (int nt = 0; nt < 3; nt++) {
                    unsigned b0 = wsu[(nt * 8 + g) * WS_LD + kg];
                    unsigned b1 = wsu[(nt * 8 + g) * WS_LD + kg + 4];
                    mma8(acc[nt], a0, a1, a2, a3, b0, b1);
                }
            }
            if (ch < 7) cpaWait0();
            __syncthreads();
        }

        float* red = ht1;
        if (kh == 1) {
#pragma unroll
            for (int n = 0; n < 3; n++)
#pragma unroll
                for (int i = 0; i < 4; i++)
                    red[(mi * 32 + lane) * 12 + n * 4 + i] = acc[n][i];
        }
        __syncthreads();
        if (kh == 0) {
#pragma unroll
            for (int n = 0; n < 3; n++)
#pragma unroll
                for (int i = 0; i < 4; i++)
                    acc[n][i] += red[(mi * 32 + lane) * 12 + n * 4 + i];

            int rbase = 16 * mi + g;
#pragma unroll
            for (int half = 0; half < 2; half++) {
                int row = rbase + half * 8;
                float gr0 = acc[0][2 * half], gr1 = acc[0][2 * half + 1];
                float gz0 = acc[1][2 * half], gz1 = acc[1][2 * half + 1];
                float gn0 = acc[2][2 * half], gn1 = acc[2][2 * half + 1];
                const float* gi = giB + ((size_t)t * BB + row) * G3;
                float2 gir = *(const float2*)(gi + c0);
                float2 giz = *(const float2*)(gi + MM + c0);
                float2 gin = *(const float2*)(gi + 2 * MM + c0);
                float2 hp = __ldcg((const float2*)(hin + (size_t)row * MM + c0));
                float R0 = sigf(gir.x + gr0 + br0);
                float R1 = sigf(gir.y + gr1 + br1);
                float Z0 = sigf(giz.x + gz0 + bz0);
                float Z1 = sigf(giz.y + gz1 + bz1);
                float N0 = tanhf(gin.x + R0 * (gn0 + bn0));
                float N1 = tanhf(gin.y + R1 * (gn1 + bn1));
                float2 ho = {(1.f - Z0) * N0 + Z0 * hp.x, (1.f - Z1) * N1 + Z1 * hp.y};
                *(float2*)(hout + (size_t)row * MM + c0) = ho;
                float2 hoT = {__uint_as_float(cvtTF(ho.x)), __uint_as_float(cvtTF(ho.y))};
                *(float2*)(houtT + (size_t)row * MM + c0) = hoT;
                if (seq) *(float2*)(seq + ((size_t)t * BB + row) * MM + c0) = ho;
            }
        }
        gbar();
    }
}

// ================= decoder GRU phase: tf32 MMA, cp.async 128-k ==============
#define ALD 132
__device__ __forceinline__ void phase_gru_mma(
    const float* xT, int Kx, const float* WihT,
    const float* hin, const float* hinT,
    float* hout, float* houtT, const float* WhhT,
    const float* bih, const float* bhh,
    float* sm, int tid)
{
    float* wc0 = sm;                  // 24*132 = 3168
    float* wc1 = sm + 3168;
    float* ac0 = sm + 6336;           // 64*132 = 8448
    float* ac1 = ac0 + 8448;
    unsigned uwc0 = s2u(wc0), uwc1 = s2u(wc1);
    unsigned uac0 = s2u(ac0), uac1 = s2u(ac1);
    int lane = tid & 31, warp = tid >> 5;
    int g = lane >> 2, t4 = lane & 3;
    int mi = warp & 3, kh = warp >> 2;
    int cBase = blockIdx.x * 8;
    int xc = Kx / 128;
    int NC = xc + 8;
    int srow = tid >> 5, skq = tid & 31;
    int wrow = tid >> 5, wi = tid & 31;   // weights: rows 0..23 handled by 3 iters of 8

    float accI[3][4], accH[3][4];
#pragma unroll
    for (int n = 0; n < 3; n++)
#pragma unroll
        for (int i = 0; i < 4; i++) { accI[n][i] = 0.f; accH[n][i] = 0.f; }

    // stage chunk 0
#pragma unroll
    for (int i = 0; i < 8; i++) {
        int row = srow + i * 8;
        cpa16(uac0 + (row * ALD + skq * 4) * 4, xT + (size_t)row * Kx + skq * 4);
    }
#pragma unroll
    for (int i = 0; i < 3; i++) {
        int row = wrow + i * 8;
        int gRow = (row >> 3) * MM + cBase + (row & 7);
        cpa16(uwc0 + (row * ALD + wi * 4) * 4, WihT + (size_t)gRow * Kx + wi * 4);
    }
    cpaCommit();
    cpaWait0();
    __syncthreads();

#pragma unroll 1
    for (int ch = 0; ch < NC; ch++) {
        float* ac  = (ch & 1) ? ac1 : ac0;
        float* wc  = (ch & 1) ? wc1 : wc0;
        unsigned uacn = (ch & 1) ? uac0 : uac1;
        unsigned uwcn = (ch & 1) ? uwc0 : uwc1;
        if (ch + 1 < NC) {
            int nc = ch + 1;
            const float* asrc; const float* wsrc; int K2, off;
            if (nc < xc) { asrc = xT;   wsrc = WihT; K2 = Kx; off = nc * 128; }
            else         { asrc = hinT; wsrc = WhhT; K2 = MM; off = (nc - xc) * 128; }
#pragma unroll
            for (int i = 0; i < 8; i++) {
                int row = srow + i * 8;
                cpa16(uacn + (row * ALD + skq * 4) * 4, asrc + (size_t)row * K2 + off + skq * 4);
            }
#pragma unroll
            for (int i = 0; i < 3; i++) {
                int row = wrow + i * 8;
                int gRow = (row >> 3) * MM + cBase + (row & 7);
                cpa16(uwcn + (row * ALD + wi * 4) * 4, wsrc + (size_t)gRow * K2 + off + wi * 4);
            }
            cpaCommit();
        }
        const unsigned* au = (const unsigned*)ac;
        const unsigned* wu = (const unsigned*)wc;
        int arow0 = (16 * mi + g) * ALD;
        int arow1 = arow0 + 8 * ALD;
        float (*acc)[4] = (ch < xc) ? accI : accH;
#pragma unroll
        for (int j = 0; j < 8; j++) {
            int k0 = (2 * j + kh) * 8;
            unsigned a0 = au[arow0 + k0 + t4];
            unsigned a1 = au[arow1 + k0 + t4];
            unsigned a2 = au[arow0 + k0 + t4 + 4];
            unsigned a3 = au[arow1 + k0 + t4 + 4];
#pragma unroll
            for (int nt = 0; nt < 3; nt++) {
                unsigned b0 = wu[(nt * 8 + g) * ALD + k0 + t4];
                unsigned b1 = wu[(nt * 8 + g) * ALD + k0 + t4 + 4];
                mma8(acc[nt], a0, a1, a2, a3, b0, b1);
            }
        }
        if (ch + 1 < NC) cpaWait0();
        __syncthreads();
    }

    float* red = ac0;
    if (kh == 1) {
#pragma unroll
        for (int n = 0; n < 3; n++)
#pragma unroll
            for (int i = 0; i < 4; i++) {
                red[(mi * 32 + lane) * 24 + n * 4 + i]      = accI[n][i];
                red[(mi * 32 + lane) * 24 + 12 + n * 4 + i] = accH[n][i];
            }
    }
    __syncthreads();
    if (kh == 0) {
#pragma unroll
        for (int n = 0; n < 3; n++)
#pragma unroll
            for (int i = 0; i < 4; i++) {
                accI[n][i] += red[(mi * 32 + lane) * 24 + n * 4 + i];
                accH[n][i] += red[(mi * 32 + lane) * 24 + 12 + n * 4 + i];
            }
        int c0 = cBase + 2 * t4;
        float2 bri = *(const float2*)(bih + c0);
        float2 bzi = *(const float2*)(bih + MM + c0);
        float2 bni = *(const float2*)(bih + 2 * MM + c0);
        float2 brh = *(const float2*)(bhh + c0);
        float2 bzh = *(const float2*)(bhh + MM + c0);
        float2 bnh = *(const float2*)(bhh + 2 * MM + c0);
#pragma unroll
        for (int half = 0; half < 2; half++) {
            int row = 16 * mi + g + half * 8;
            float2 hp = __ldcg((const float2*)(hin + (size_t)row * MM + c0));
            float R0 = sigf(accI[0][2*half]   + bri.x + accH[0][2*half]   + brh.x);
            float R1 = sigf(accI[0][2*half+1] + bri.y + accH[0][2*half+1] + brh.y);
            float Z0 = sigf(accI[1][2*half]   + bzi.x + accH[1][2*half]   + bzh.x);
            float Z1 = sigf(accI[1][2*half+1] + bzi.y + accH[1][2*half+1] + bzh.y);
            float N0 = tanhf(accI[2][2*half]   + bni.x + R0 * (accH[2][2*half]   + bnh.x));
            float N1 = tanhf(accI[2][2*half+1] + bni.y + R1 * (accH[2][2*half+1] + bnh.y));
            float2 ho = {(1.f - Z0) * N0 + Z0 * hp.x, (1.f - Z1) * N1 + Z1 * hp.y};
            *(float2*)(hout + (size_t)row * MM + c0) = ho;
            float2 hoT = {__uint_as_float(cvtTF(ho.x)), __uint_as_float(cvtTF(ho.y))};
            *(float2*)(houtT + (size_t)row * MM + c0) = hoT;
        }
    }
}

// ================= fc1: tf32 MMA, cp.async 128-k ============================
__device__ __forceinline__ void phase_fc1_mma(
    const float* AT, const float* WT, const float* bias, float* sm, int tid)
{
    float* wc0 = sm;                 // 16*132 = 2112
    float* wc1 = sm + 2112;
    float* ac0 = sm + 4224;          // 8448
    float* ac1 = ac0 + 8448;
    unsigned uwc0 = s2u(wc0), uwc1 = s2u(wc1);
    unsigned uac0 = s2u(ac0), uac1 = s2u(ac1);
    int lane = tid & 31, warp = tid >> 5;
    int g = lane >> 2, t4 = lane & 3;
    int mi = warp & 3, kh = warp >> 2;
    int cBase = blockIdx.x * 16;
    int srow = tid >> 5, skq = tid & 31;

    float acc[2][4];
#pragma unroll
    for (int n = 0; n < 2; n++)
#pragma unroll
        for (int i = 0; i < 4; i++) acc[n][i] = 0.f;

#pragma unroll
    for (int i = 0; i < 8; i++) {
        int row = srow + i * 8;
        cpa16(uac0 + (row * ALD + skq * 4) * 4, AT + (size_t)row * MM + skq * 4);
    }
#pragma unroll
    for (int i = 0; i < 2; i++) {
        int row = srow + i * 8;
        cpa16(uwc0 + (row * ALD + skq * 4) * 4, WT + (size_t)(cBase + row) * MM + skq * 4);
    }
    cpaCommit();
    cpaWait0();
    __syncthreads();

#pragma unroll 1
    for (int ch = 0; ch < 8; ch++) {
        float* ac  = (ch & 1) ? ac1 : ac0;
        float* wc  = (ch & 1) ? wc1 : wc0;
        unsigned uacn = (ch & 1) ? uac0 : uac1;
        unsigned uwcn = (ch & 1) ? uwc0 : uwc1;
        if (ch < 7) {
            int off = (ch + 1) * 128;
#pragma unroll
            for (int i = 0; i < 8; i++) {
                int row = srow + i * 8;
                cpa16(uacn + (row * ALD + skq * 4) * 4, AT + (size_t)row * MM + off + skq * 4);
            }
#pragma unroll
            for (int i = 0; i < 2; i++) {
                int row = srow + i * 8;
                cpa16(uwcn + (row * ALD + skq * 4) * 4, WT + (size_t)(cBase + row) * MM + off + skq * 4);
            }
            cpaCommit();
        }
        const unsigned* au = (const unsigned*)ac;
        const unsigned* wu = (const unsigned*)wc;
        int arow0 = (16 * mi + g) * ALD;
        int arow1 = arow0 + 8 * ALD;
#pragma unroll
        for (int j = 0; j < 8; j++) {
            int k0 = (2 * j + kh) * 8;
            unsigned a0 = au[arow0 + k0 + t4];
            unsigned a1 = au[arow1 + k0 + t4];
            unsigned a2 = au[arow0 + k0 + t4 + 4];
            unsigned a3 = au[arow1 + k0 + t4 + 4];
#pragma unroll
            for (int nt = 0; nt < 2; nt++) {
                unsigned b0 = wu[(nt * 8 + g) * ALD + k0 + t4];
                unsigned b1 = wu[(nt * 8 + g) * ALD + k0 + t4 + 4];
                mma8(acc[nt], a0, a1, a2, a3, b0, b1);
            }
        }
        if (ch < 7) cpaWait0();
        __syncthreads();
    }

    float* red = ac0;
    if (kh == 1) {
#pragma unroll
        for (int n = 0; n < 2; n++)
#pragma unroll
            for (int i = 0; i < 4; i++)
                red[(mi * 32 + lane) * 8 + n * 4 + i] = acc[n][i];
    }
    __syncthreads();
    if (kh == 0) {
#pragma unroll
        for (int n = 0; n < 2; n++)
#pragma unroll
            for (int i = 0; i < 4; i++)
                acc[n][i] += red[(mi * 32 + lane) * 8 + n * 4 + i];
#pragma unroll
        for (int half = 0; half < 2; half++) {
            int row = 16 * mi + g + half * 8;
#pragma unroll
            for (int nt = 0; nt < 2; nt++) {
                int c = cBase + nt * 8 + 2 * t4;
                float2 bv = *(const float2*)(bias + c);
                float2 o = {acc[nt][2 * half] + bv.x, acc[nt][2 * half + 1] + bv.y};
                *(float2*)(g_zpre + (size_t)row * LMM + c) = o;
            }
        }
    }
}

// ================= fc2: tf32 MMA, K-split + hi/lo, cp.async 128-k ===========
__device__ __forceinline__ void phase_fc2_mma(const float* WT, float* sm, int tid)
{
    float* wc0 = sm;                 // 8*132 = 1056
    float* wc1 = sm + 1056;
    float* hi0 = sm + 2112;          // 8448 each
    float* lo0 = hi0 + 8448;
    float* hi1 = lo0 + 8448;
    float* lo1 = hi1 + 8448;
    unsigned uwc0 = s2u(wc0), uwc1 = s2u(wc1);
    unsigned uhi0 = s2u(hi0), ulo0 = s2u(lo0);
    unsigned uhi1 = s2u(hi1), ulo1 = s2u(lo1);
    int lane = tid & 31, warp = tid >> 5;
    int g = lane >> 2, t4 = lane & 3;
    int mi = warp & 3, kh = warp >> 2;
    int cBase = (blockIdx.x >> 1) * 8;
    int ksp = blockIdx.x & 1;
    int kOff = ksp * 1024;
    int srow = tid >> 5, skq = tid & 31;

    float acc[4] = {0.f, 0.f, 0.f, 0.f};

#pragma unroll
    for (int i = 0; i < 8; i++) {
        int row = srow + i * 8;
        cpa16(uhi0 + (row * ALD + skq * 4) * 4, g_zhi + (size_t)row * LMM + kOff + skq * 4);
        cpa16(ulo0 + (row * ALD + skq * 4) * 4, g_zlo + (size_t)row * LMM + kOff + skq * 4);
    }
    if (tid < 256) {
        int row = tid >> 5;
        cpa16(uwc0 + (row * ALD + skq * 4) * 4, WT + (size_t)(cBase + row) * LMM + kOff + skq * 4);
    }
    cpaCommit();
    cpaWait0();
    __syncthreads();

#pragma unroll 1
    for (int ch = 0; ch < 8; ch++) {
        float* hi  = (ch & 1) ? hi1 : hi0;
        float* lo  = (ch & 1) ? lo1 : lo0;
        float* wc  = (ch & 1) ? wc1 : wc0;
        unsigned uhin = (ch & 1) ? uhi0 : uhi1;
        unsigned ulon = (ch & 1) ? ulo0 : ulo1;
        unsigned uwcn = (ch & 1) ? uwc0 : uwc1;
        if (ch < 7) {
            int off = kOff + (ch + 1) * 128;
#pragma unroll
            for (int i = 0; i < 8; i++) {
                int row = srow + i * 8;
                cpa16(uhin + (row * ALD + skq * 4) * 4, g_zhi + (size_t)row * LMM + off + skq * 4);
                cpa16(ulon + (row * ALD + skq * 4) * 4, g_zlo + (size_t)row * LMM + off + skq * 4);
            }
            {
                int row = tid >> 5;
                cpa16(uwcn + (row * ALD + skq * 4) * 4, WT + (size_t)(cBase + row) * LMM + off + skq * 4);
            }
            cpaCommit();
        }
        const unsigned* hu = (const unsigned*)hi;
        const unsigned* lu = (const unsigned*)lo;
        const unsigned* wu = (const unsigned*)wc;
        int arow0 = (16 * mi + g) * ALD;
        int arow1 = arow0 + 8 * ALD;
#pragma unroll
        for (int j = 0; j < 8; j++) {
            int k0 = (2 * j + kh) * 8;
            unsigned b0 = wu[g * ALD + k0 + t4];
            unsigned b1 = wu[g * ALD + k0 + t4 + 4];
            mma8(acc, hu[arow0 + k0 + t4], hu[arow1 + k0 + t4],
                      hu[arow0 + k0 + t4 + 4], hu[arow1 + k0 + t4 + 4], b0, b1);
            mma8(acc, lu[arow0 + k0 + t4], lu[arow1 + k0 + t4],
                      lu[arow0 + k0 + t4 + 4], lu[arow1 + k0 + t4 + 4], b0, b1);
        }
        if (ch < 7) cpaWait0();
        __syncthreads();
    }

    float* red = hi0;
    if (kh == 1) {
#pragma unroll
        for (int i = 0; i < 4; i++)
            red[(mi * 32 + lane) * 4 + i] = acc[i];
    }
    __syncthreads();
    if (kh == 0) {
#pragma unroll
        for (int i = 0; i < 4; i++) acc[i] += red[(mi * 32 + lane) * 4 + i];
        int c0 = cBase + 2 * t4;
#pragma unroll
        for (int half = 0; half < 2; half++) {
            int row = 16 * mi + g + half * 8;
            float2 o = {acc[2 * half], acc[2 * half + 1]};
            *(float2*)(g_l2p + (size_t)ksp * BB * OO + (size_t)row * OO + c0) = o;
        }
    }
}

// ---------------- ln / softmax ----------------
__device__ __forceinline__ void phase_ln(const float* g, const float* bta, int tid)
{
    int b = blockIdx.x;
    float v[8];
    float s = 0.f, s2 = 0.f;
#pragma unroll
    for (int j = 0; j < 8; j++) {
        float t = __ldcg(&g_zpre[(size_t)b * LMM + tid + j * 256]);
        v[j] = t; s += t; s2 += t * t;
    }
    __shared__ float red[64];
#pragma unroll
    for (int o = 16; o; o >>= 1) {
        s += __shfl_down_sync(0xffffffffu, s, o);
        s2 += __shfl_down_sync(0xffffffffu, s2, o);
    }
    int w = tid >> 5, l = tid & 31;
    if (l == 0) { red[w] = s; red[32 + w] = s2; }
    __syncthreads();
    if (tid == 0) {
        float a = 0.f, a2 = 0.f;
        for (int i = 0; i < 8; i++) { a += red[i]; a2 += red[32 + i]; }
        red[0] = a; red[32] = a2;
    }
    __syncthreads();
    float mu = red[0] * (1.f / (float)LMM);
    float var = red[32] * (1.f / (float)LMM) - mu * mu;
    float rs = rsqrtf(var + 1e-5f);
#pragma unroll
    for (int j = 0; j < 8; j++) {
        int cc = tid + j * 256;
        float t = (v[j] - mu) * rs * g[cc] + bta[cc];
        float z = t * normcdff(t);
        float zh = __uint_as_float(cvtTF(z));
        float zl = __uint_as_float(cvtTF(z - zh));
        g_zhi[(size_t)b * LMM + cc] = zh;
        g_zlo[(size_t)b * LMM + cc] = zl;
    }
}

__device__ __forceinline__ void phase_softmax2(
    float* out, int s, float* youtT, const float* fc2b, int tid)
{
    int b = blockIdx.x;
    float v0 = __ldcg(&g_l2p[(size_t)b * OO + tid])
             + __ldcg(&g_l2p[(size_t)BB * OO + b * OO + tid]) + fc2b[tid];
    float v1 = __ldcg(&g_l2p[(size_t)b * OO + 256 + tid])
             + __ldcg(&g_l2p[(size_t)BB * OO + b * OO + 256 + tid]) + fc2b[256 + tid];
    out[((size_t)b * TDEC + s) * OO + tid] = v0;
    out[((size_t)b * TDEC + s) * OO + 256 + tid] = v1;

    __shared__ float sred[9];
    int w = tid >> 5, l = tid & 31;
    float m = fmaxf(v0, v1);
#pragma unroll
    for (int d = 16; d; d >>= 1) m = fmaxf(m, __shfl_down_sync(0xffffffffu, m, d));
    if (l == 0) sred[w] = m;
    __syncthreads();
    if (tid == 0) {
        float a = sred[0];
        for (int i = 1; i < 8; i++) a = fmaxf(a, sred[i]);
        sred[8] = a;
    }
    __syncthreads();
    float mx = sred[8];
    float e0 = expf(v0 - mx), e1 = expf(v1 - mx);
    float su = e0 + e1;
#pragma unroll
    for (int d = 16; d; d >>= 1) su += __shfl_down_sync(0xffffffffu, su, d);
    __syncthreads();
    if (l == 0) sred[w] = su;
    __syncthreads();
    if (tid == 0) {
        float a = 0.f;
        for (int i = 0; i < 8; i++) a += sred[i];
        sred[8] = a;
    }
    __syncthreads();
    float inv = 1.f / sred[8];
    youtT[(size_t)b * OO + tid]       = __uint_as_float(cvtTF(e0 * inv));
    youtT[(size_t)b * OO + 256 + tid] = __uint_as_float(cvtTF(e1 * inv));
}

__global__ void __launch_bounds__(256) dec_persist(
    float* __restrict__ out,
    float* yTA, float* yTB,
    float* h0A, float* h0B, float* h0TA, float* h0TB,
    float* h1A, float* h1B, float* h1TA, float* h1TB,
    const float* __restrict__ bih0, const float* __restrict__ bhh0,
    const float* __restrict__ bih1, const float* __restrict__ bhh1,
    const float* __restrict__ fc1b,
    const float* __restrict__ lng, const float* __restrict__ lnb,
    const float* __restrict__ fc2b)
{
    extern __shared__ float sm[];
    int tid = threadIdx.x;

    for (int s = 0; s < TDEC; s++) {
        const float* yinT = (s & 1) ? yTB : yTA;
        float* youtT      = (s & 1) ? yTA : yTB;
        const float* h0i  = (s & 1) ? h0B : h0A;
        const float* h0iT = (s & 1) ? h0TB : h0TA;
        float* h0o        = (s & 1) ? h0A : h0B;
        float* h0oT       = (s & 1) ? h0TA : h0TB;
        const float* h1i  = (s & 1) ? h1B : h1A;
        const float* h1iT = (s & 1) ? h1TB : h1TA;
        float* h1o        = (s & 1) ? h1A : h1B;
        float* h1oT       = (s & 1) ? h1TA : h1TB;

        phase_gru_mma(yinT, OO, g_tWih0, h0i, h0iT, h0o, h0oT, g_tWhh0, bih0, bhh0, sm, tid);
        gbar();
        phase_gru_mma(h0oT, MM, g_tWih1, h1i, h1iT, h1o, h1oT, g_tWhh1, bih1, bhh1, sm, tid);
        gbar();
        phase_fc1_mma(h1oT, g_tfc1, fc1b, sm, tid);
        gbar();
        if (blockIdx.x < BB) phase_ln(lng, lnb, tid);
        gbar();
        phase_fc2_mma(g_tfc2, sm, tid);
        gbar();
        if (blockIdx.x < BB) phase_softmax2(out, s, youtT, fc2b, tid);
        gbar();
    }
}

// ---------------- init / transpose / cvt / big GEMM ------------
__global__ void zero_init_kernel() {
    int i = blockIdx.x * blockDim.x + threadIdx.x;
    int stride = gridDim.x * blockDim.x;
    for (; i < BB * MM; i += stride) {
        g_e0A[i] = 0.f; g_e1A[i] = 0.f;
        g_hT0A[i] = 0.f; g_hT1A[i] = 0.f;
    }
}
__global__ void copy_y_kernel(const float* __restrict__ Y0) {
    int i = blockIdx.x * blockDim.x + threadIdx.x;
    if (i < BB * OO) g_yTA[i] = __uint_as_float(cvtTF(Y0[i]));
}
__global__ void transpose_x_kernel(const float* __restrict__ X) {
    int i = blockIdx.x * blockDim.x + threadIdx.x;
    int stride = gridDim.x * blockDim.x;
    const int total = TIN * BB * NIN;
    for (; i < total; i += stride) {
        int n = i % NIN;
        int r = i / NIN;
        int t = r / BB, b = r % BB;
        g_xt[i] = X[(b * TIN + t) * NIN + n];
    }
}
__global__ void cvt_w_kernel(const float* __restrict__ s, float* __restrict__ d, int n) {
    int i = blockIdx.x * blockDim.x + threadIdx.x;
    int st = gridDim.x * blockDim.x;
    for (; i < n; i += st) d[i] = __uint_as_float(cvtTF(s[i]));
}

__device__ __forceinline__ void fma2(ull& d, ull a, ull b) {
    asm("fma.rn.f32x2 %0, %1, %2, %0;" : "+l"(d) : "l"(a), "l"(b));
}

__global__ void __launch_bounds__(256) gemm_big_kernel(
    const float* __restrict__ A, const float* __restrict__ W,
    const float* __restrict__ bias, float* __restrict__ C,
    int K, int Cn)
{
    __shared__ __align__(16) float As[16][132];
    __shared__ __align__(16) float Bs[16][132];
    int tid = threadIdx.x;
    int tx = tid & 15, ty = tid >> 4;
    int r0 = blockIdx.y * 128, c0 = blockIdx.x * 128;
    ull acc[8][4];
#pragma unroll
    for (int i = 0; i < 8; i++)
#pragma unroll
        for (int j = 0; j < 4; j++) acc[i][j] = 0ull;
    for (int k0 = 0; k0 < K; k0 += 16) {
#pragma unroll
        for (int i = 0; i < 2; i++) {
            int q = tid + i * 256;
            int rr = q >> 2, kq = q & 3;
            float4 v = *(const float4*)(A + (size_t)(r0 + rr) * K + k0 + kq * 4);
            As[kq * 4 + 0][rr] = v.x; As[kq * 4 + 1][rr] = v.y;
            As[kq * 4 + 2][rr] = v.z; As[kq * 4 + 3][rr] = v.w;
        }
#pragma unroll
        for (int i = 0; i < 2; i++) {
            int q = tid + i * 256;
            int wn = q >> 2, kq = q & 3;
            float4 v = *(const float4*)(W + (size_t)(c0 + wn) * K + k0 + kq * 4);
            Bs[kq * 4 + 0][wn] = v.x; Bs[kq * 4 + 1][wn] = v.y;
            Bs[kq * 4 + 2][wn] = v.z; Bs[kq * 4 + 3][wn] = v.w;
        }
        __syncthreads();
#pragma unroll
        for (int kk = 0; kk < 16; kk++) {
            ulonglong2 bq0 = *(ulonglong2*)&Bs[kk][tx * 8];
            ulonglong2 bq1 = *(ulonglong2*)&Bs[kk][tx * 8 + 4];
            ull bp[4] = {bq0.x, bq0.y, bq1.x, bq1.y};
            float4 a0 = *(float4*)&As[kk][ty * 8];
            float4 a1 = *(float4*)&As[kk][ty * 8 + 4];
            float av[8] = {a0.x, a0.y, a0.z, a0.w, a1.x, a1.y, a1.z, a1.w};
#pragma unroll
            for (int i = 0; i < 8; i++) {
                ull ap;
                asm("mov.b64 %0, {%1,%1};" : "=l"(ap) : "f"(av[i]));
#pragma unroll
                for (int j = 0; j < 4; j++) fma2(acc[i][j], ap, bp[j]);
            }
        }
        __syncthreads();
    }
    int c = c0 + tx * 8;
    float4 bv0 = *(const float4*)(bias + c);
    float4 bv1 = *(const float4*)(bias + c + 4);
#pragma unroll
    for (int i = 0; i < 8; i++) {
        int r = r0 + ty * 8 + i;
        float2 p0, p1, p2, p3;
        asm("mov.b64 {%0,%1}, %2;" : "=f"(p0.x), "=f"(p0.y) : "l"(acc[i][0]));
        asm("mov.b64 {%0,%1}, %2;" : "=f"(p1.x), "=f"(p1.y) : "l"(acc[i][1]));
        asm("mov.b64 {%0,%1}, %2;" : "=f"(p2.x), "=f"(p2.y) : "l"(acc[i][2]));
        asm("mov.b64 {%0,%1}, %2;" : "=f"(p3.x), "=f"(p3.y) : "l"(acc[i][3]));
        float4 o0 = {p0.x + bv0.x, p0.y + bv0.y, p1.x + bv0.z, p1.y + bv0.w};
        float4 o1 = {p2.x + bv1.x, p2.y + bv1.y, p3.x + bv1.z, p3.y + bv1.w};
        *(float4*)(C + (size_t)r * Cn + c) = o0;
        *(float4*)(C + (size_t)r * Cn + c + 4) = o1;
    }
}

// ---------------- host launch ----------------
#define DEC_SM ((2 * 1056 + 4 * 8448) * 4)      // 143616 B (fc2 max)

extern "C" void kernel_launch(void* const* d_in, const int* in_sizes, int n_in,
                              void* d_out, int out_size)
{
    const float* X        = (const float*)d_in[0];
    const float* Y0       = (const float*)d_in[1];
    const float* enc_Wih0 = (const float*)d_in[2];
    const float* enc_Whh0 = (const float*)d_in[3];
    const float* enc_bih0 = (const float*)d_in[4];
    const float* enc_bhh0 = (const float*)d_in[5];
    const float* enc_Wih1 = (const float*)d_in[6];
    const float* enc_Whh1 = (const float*)d_in[7];
    const float* enc_bih1 = (const float*)d_in[8];
    const float* enc_bhh1 = (const float*)d_in[9];
    const float* dec_Wih0 = (const float*)d_in[10];
    const float* dec_Whh0 = (const float*)d_in[11];
    const float* dec_bih0 = (const float*)d_in[12];
    const float* dec_bhh0 = (const float*)d_in[13];
    const float* dec_Wih1 = (const float*)d_in[14];
    const float* dec_Whh1 = (const float*)d_in[15];
    const float* dec_bih1 = (const float*)d_in[16];
    const float* dec_bhh1 = (const float*)d_in[17];
    const float* fc1_w    = (const float*)d_in[18];
    const float* fc1_b    = (const float*)d_in[19];
    const float* ln_g     = (const float*)d_in[20];
    const float* ln_b     = (const float*)d_in[21];
    const float* fc2_w    = (const float*)d_in[22];
    const float* fc2_b    = (const float*)d_in[23];
    float* out = (float*)d_out;

    float *xt, *gi, *seq0, *e0A, *e0B, *e1A, *e1B, *yTA, *yTB;
    float *hT0A, *hT0B, *hT1A, *hT1B;
    float *tWih0, *tWhh0, *tWih1, *tWhh1, *tfc1, *tfc2;
    cudaGetSymbolAddress((void**)&xt,   g_xt);
    cudaGetSymbolAddress((void**)&gi,   g_gi);
    cudaGetSymbolAddress((void**)&seq0, g_seq0);
    cudaGetSymbolAddress((void**)&e0A,  g_e0A);
    cudaGetSymbolAddress((void**)&e0B,  g_e0B);
    cudaGetSymbolAddress((void**)&e1A,  g_e1A);
    cudaGetSymbolAddress((void**)&e1B,  g_e1B);
    cudaGetSymbolAddress((void**)&hT0A, g_hT0A);
    cudaGetSymbolAddress((void**)&hT0B, g_hT0B);
    cudaGetSymbolAddress((void**)&hT1A, g_hT1A);
    cudaGetSymbolAddress((void**)&hT1B, g_hT1B);
    cudaGetSymbolAddress((void**)&yTA,  g_yTA);
    cudaGetSymbolAddress((void**)&yTB,  g_yTB);
    cudaGetSymbolAddress((void**)&tWih0, g_tWih0);
    cudaGetSymbolAddress((void**)&tWhh0, g_tWhh0);
    cudaGetSymbolAddress((void**)&tWih1, g_tWih1);
    cudaGetSymbolAddress((void**)&tWhh1, g_tWhh1);
    cudaGetSymbolAddress((void**)&tfc1, g_tfc1);
    cudaGetSymbolAddress((void**)&tfc2, g_tfc2);

    cudaFuncSetAttribute(enc_mma,     cudaFuncAttributeMaxDynamicSharedMemorySize, ENC2_SM);
    cudaFuncSetAttribute(dec_persist, cudaFuncAttributeMaxDynamicSharedMemorySize, DEC_SM);

    zero_init_kernel<<<256, 256>>>();
    copy_y_kernel<<<(BB * OO + 255) / 256, 256>>>(Y0);
    transpose_x_kernel<<<2048, 256>>>(X);
    cvt_w_kernel<<<1024, 256>>>(dec_Wih0, tWih0, G3 * OO);
    cvt_w_kernel<<<1024, 256>>>(dec_Whh0, tWhh0, G3 * MM);
    cvt_w_kernel<<<1024, 256>>>(dec_Wih1, tWih1, G3 * MM);
    cvt_w_kernel<<<1024, 256>>>(dec_Whh1, tWhh1, G3 * MM);
    cvt_w_kernel<<<1024, 256>>>(fc1_w, tfc1, LMM * MM);
    cvt_w_kernel<<<1024, 256>>>(fc2_w, tfc2, OO * LMM);

    const int R = TIN * BB;

    // encoder layer 0
    gemm_big_kernel<<<dim3(G3 / 128, R / 128), 256>>>(xt, enc_Wih0, enc_bih0, gi, NIN, G3);
    {
        const float* w = enc_Whh0; const float* b = enc_bhh0; const float* gp = gi;
        float* hA = e0A; float* hB = e0B; float* hTA = hT0A; float* hTB = hT0B; float* sq = seq0;
        void* args[] = {&w, &b, &gp, &hA, &hB, &hTA, &hTB, &sq};
        cudaLaunchCooperativeKernel((void*)enc_mma, dim3(128), dim3(256), args, (size_t)ENC2_SM, (cudaStream_t)0);
    }

    // encoder layer 1
    gemm_big_kernel<<<dim3(G3 / 128, R / 128), 256>>>(seq0, enc_Wih1, enc_bih1, gi, MM, G3);
    {
        const float* w = enc_Whh1; const float* b = enc_bhh1; const float* gp = gi;
        float* hA = e1A; float* hB = e1B; float* hTA = hT1A; float* hTB = hT1B; float* sq = nullptr;
        void* args[] = {&w, &b, &gp, &hA, &hB, &hTA, &hTB, &sq};
        cudaLaunchCooperativeKernel((void*)enc_mma, dim3(128), dim3(256), args, (size_t)ENC2_SM, (cudaStream_t)0);
    }

    // decoder: one persistent kernel, all 64 steps
    {
        float* outp = out;
        void* args[] = {&outp, &yTA, &yTB,
                        &e0A, &e0B, &hT0A, &hT0B,
                        &e1A, &e1B, &hT1A, &hT1B,
                        (void*)&dec_bih0, (void*)&dec_bhh0,
                        (void*)&dec_bih1, (void*)&dec_bhh1,
                        (void*)&fc1_b, (void*)&ln_g, (void*)&ln_b, (void*)&fc2_b};
        cudaLaunchCooperativeKernel((void*)dec_persist, dim3(128), dim3(256), args, (size_t)DEC_SM, (cudaStream_t)0);
    }
}